// round 7
// baseline (speedup 1.0000x reference)
#include <cuda_runtime.h>

// Problem constants
#define NB     32
#define TT     4096
#define ENC_H  512
#define ATT_H  256
#define OUTD   80
#define SPK    64
#define KW     31
#define NWMAX  19

#define NPRE   32                  // prenet blocks (bids 0..31 -> wave-1 resident)
#define NCG    16                  // channel groups per batch (16 ch each)
#define NWB    (NB * NCG)          // 512 window blocks
#define GRID   (NPRE + NWB)        // 544

// Device scratch (no allocations allowed). All zero-init; self-resetting.
__device__ unsigned d_cnt1  = 0, d_cnt1b = 0;   // h ready / stage2-done handshake
__device__ unsigned d_cnt2  = 0, d_cnt2b = 0;   // pout ready / consumed handshake
__device__ unsigned d_count[NB];                // softmax gate (reset by last block)
__device__ float    d_bias0[NB][ATT_H];
__device__ float    d_h[1024][NB];              // prenet layer-1, k-major
__device__ float    d_pout[512][NB];            // prenet layer-2 out, k-major
__device__ float    d_logit_part[NB][NWMAX][NCG];

union SmemU {
    struct {                                    // prenet stage 1
        float dec_s[32][145];                   // 145 % 32 = 17, conflict-free
        float w1[144][33];
    } p1;
    struct {                                    // prenet stage 2
        float h_t[128][33];
        float w2[128][17];
    } p2;
    struct {                                    // window block
        union {
            float enc_s[NWMAX][516];            // full 512-k window (39.2KB)
            struct {
                float red[NWMAX][NCG][17];      // matvec partials (after enc reads)
                float bias_red[NCG][17];
            } r;
        } u;
        float pa_s[NWMAX + 30 + 3];
        float convw[NCG * KW];
        float benc[NCG], wproj[NCG], bias_s[NCG];
        float rv[256]; int ri[256];
    } w;
};

__global__ __launch_bounds__(256) void k_fused(
    const float* __restrict__ input_enc,
    const float* __restrict__ input_dec,
    const float* __restrict__ prev_att,
    const float* __restrict__ spkr,
    const int*   __restrict__ lengths,
    const float* __restrict__ speed,
    const float* __restrict__ W_enc,
    const float* __restrict__ b_enc,
    const float* __restrict__ W_spkr,
    const float* __restrict__ conv_w,
    const float* __restrict__ W_dec,
    const float* __restrict__ W_speed,
    const float* __restrict__ Wp1,
    const float* __restrict__ bp1,
    const float* __restrict__ Wp2,
    const float* __restrict__ bp2,
    const float* __restrict__ W_proj,
    float* __restrict__ out)
{
    __shared__ SmemU sm;
    __shared__ int last_s, sh_lo, sh_nwin;
    const int tid = threadIdx.x;
    const int blk = blockIdx.x;

    // ======================= PRENET BLOCKS (0..31) =======================
    if (blk < NPRE) {
        const int p = blk;

        // bias0: channels [8p, 8p+8) x 32 batches (independent of everything)
        {
            const int bb = tid >> 3, c = p * 8 + (tid & 7);
            float sa = 0.f;
            #pragma unroll 8
            for (int k = 0; k < SPK; k++)
                sa = fmaf(spkr[bb * SPK + k], W_spkr[k * ATT_H + c], sa);
            float v = sa / (1.f + fabsf(sa));
            d_bias0[bb][c] = fmaf(speed[bb], W_speed[c], v);
        }

        // ---- stage 1: h channels [32p, 32p+32) for all 32 batches ----
        for (int i = tid; i < NB * OUTD; i += 256) {
            int b2 = i / OUTD, k = i - b2 * OUTD;
            sm.p1.dec_s[b2][k] = input_dec[i];
        }
        for (int i = tid; i < NB * SPK; i += 256) {
            int b2 = i >> 6, k = i & 63;
            sm.p1.dec_s[b2][OUTD + k] = spkr[i];
        }
        for (int i = tid; i < 144 * 32; i += 256) {
            int k = i >> 5, j = i & 31;
            sm.p1.w1[k][j] = Wp1[k * 1024 + p * 32 + j];
        }
        __syncthreads();

        {
            const int bb = tid & 31, jq = tid >> 5;
            #pragma unroll
            for (int r = 0; r < 4; r++) {
                const int j = r * 8 + jq;
                float acc = 0.f;
                #pragma unroll 8
                for (int k = 0; k < 144; k++)
                    acc = fmaf(sm.p1.dec_s[bb][k], sm.p1.w1[k][j], acc);
                d_h[p * 32 + j][bb] = fmaxf(acc + bp1[p * 32 + j], 0.f);
            }
        }
        __threadfence();
        __syncthreads();
        if (tid == 0) atomicAdd(&d_cnt1, 1u);

        // ---- stage 2: pout channels [16p, 16p+16) for all batches ----
        if (tid == 0) {
            volatile unsigned* v1 = &d_cnt1;
            while (*v1 < NPRE) { __nanosleep(32); }
        }
        __syncthreads();
        __threadfence();

        const int cp0 = p * 16;
        const int bb2 = tid & 31, j2 = (tid >> 5) * 2;
        float a0 = 0.f, a1 = 0.f;
        for (int kt = 0; kt < 8; kt++) {
            const int k0 = kt * 128;
            __syncthreads();
            for (int i = tid; i < 128 * 32; i += 256) {
                int kk = i >> 5, b2 = i & 31;
                sm.p2.h_t[kk][b2] = __ldcg(&d_h[k0 + kk][b2]);
            }
            for (int i = tid; i < 128 * 16; i += 256) {
                int kk = i >> 4, j = i & 15;
                sm.p2.w2[kk][j] = Wp2[(size_t)(k0 + kk) * 512 + cp0 + j];
            }
            __syncthreads();
            #pragma unroll 8
            for (int kk = 0; kk < 128; kk++) {
                float hv = sm.p2.h_t[kk][bb2];
                a0 = fmaf(hv, sm.p2.w2[kk][j2],     a0);
                a1 = fmaf(hv, sm.p2.w2[kk][j2 + 1], a1);
            }
        }
        d_pout[cp0 + j2][bb2]     = fmaxf(a0 + bp2[cp0 + j2],     0.f);
        d_pout[cp0 + j2 + 1][bb2] = fmaxf(a1 + bp2[cp0 + j2 + 1], 0.f);

        __threadfence();
        __syncthreads();
        if (tid == 0) {
            atomicAdd(&d_cnt2, 1u);
            // reset cnt1 after ALL 32 blocks completed stage2 (=> all passed spin)
            unsigned old = atomicAdd(&d_cnt1b, 1u);
            if (old == NPRE - 1) { d_cnt1 = 0; d_cnt1b = 0; }
        }
        return;
    }

    // ======================= WINDOW BLOCKS (32..543) =======================
    const int wi = blk - NPRE;
    const int b  = wi >> 4;
    const int cg = wi & 15;
    const int c0 = cg * 16;

    // zero this block's 1/16 output slice (256 floats)
    if (tid < 64) {
        ((float4*)(out + (size_t)b * TT + cg * 256))[tid] =
            make_float4(0.f, 0.f, 0.f, 0.f);
    }

    // full argmax of prev_att[b] (local to block; first max wins)
    {
        const float4* pa4 = (const float4*)(prev_att + (size_t)b * TT);
        float bv = -1.0f; int bi = 0;
        #pragma unroll
        for (int j = 0; j < 4; j++) {
            float4 v = pa4[tid * 4 + j];
            int base = tid * 16 + j * 4;
            if (v.x > bv) { bv = v.x; bi = base; }
            if (v.y > bv) { bv = v.y; bi = base + 1; }
            if (v.z > bv) { bv = v.z; bi = base + 2; }
            if (v.w > bv) { bv = v.w; bi = base + 3; }
        }
        sm.w.rv[tid] = bv; sm.w.ri[tid] = bi;
    }
    __syncthreads();
    for (int s = 128; s > 0; s >>= 1) {
        if (tid < s) {
            float ov = sm.w.rv[tid + s]; int oi = sm.w.ri[tid + s];
            if (ov > sm.w.rv[tid] || (ov == sm.w.rv[tid] && oi < sm.w.ri[tid])) {
                sm.w.rv[tid] = ov; sm.w.ri[tid] = oi;
            }
        }
        __syncthreads();
    }
    if (tid == 0) {
        int mi = sm.w.ri[0];
        int lo = max(mi - 9, 0);
        int hi = min(mi + 9, lengths[b] - 1);
        sh_lo = lo; sh_nwin = hi - lo + 1;
    }
    __syncthreads();
    const int lo   = sh_lo;
    const int nwin = sh_nwin;

    // stage enc window (19 x 512 floats), pa halo, conv weights, small vectors
    {
        const float4* enc4 = (const float4*)(input_enc + (size_t)b * TT * ENC_H);
        for (int i = tid; i < NWMAX * 128; i += 256) {
            int t = i >> 7, q = i & 127;
            int row = lo + t; if (row > TT - 1) row = TT - 1;   // clamped; unused t>=nwin
            float4 e = enc4[(size_t)row * (ENC_H / 4) + q];
            *(float4*)&sm.w.u.enc_s[t][q * 4] = e;
        }
        for (int i = tid; i < nwin + 30; i += 256) {
            int p2 = lo - 15 + i;
            sm.w.pa_s[i] = (p2 >= 0 && p2 < TT) ? prev_att[(size_t)b * TT + p2] : 0.f;
        }
        for (int i = tid; i < NCG * KW; i += 256) sm.w.convw[i] = conv_w[c0 * KW + i];
        if (tid < NCG) {
            sm.w.benc[tid]  = b_enc[c0 + tid];
            sm.w.wproj[tid] = W_proj[c0 + tid];
        }
    }
    __syncthreads();

    // matvec: cl = tid&15 -> channel c0+cl; kq = tid>>4 -> 32-k split
    const int cl = tid & 15;
    const int kq = tid >> 4;
    const int ca = c0 + cl;

    float acc[NWMAX];
    #pragma unroll
    for (int t = 0; t < NWMAX; t++) acc[t] = 0.f;

    #pragma unroll
    for (int k4 = 0; k4 < 8; k4++) {
        const int k = kq * 32 + k4 * 4;
        float4 wa;
        wa.x = W_enc[(k + 0) * ATT_H + ca];
        wa.y = W_enc[(k + 1) * ATT_H + ca];
        wa.z = W_enc[(k + 2) * ATT_H + ca];
        wa.w = W_enc[(k + 3) * ATT_H + ca];
        #pragma unroll
        for (int t = 0; t < NWMAX; t++) {
            float4 e = *(const float4*)&sm.w.u.enc_s[t][k];
            acc[t] = fmaf(e.x, wa.x, acc[t]);
            acc[t] = fmaf(e.y, wa.y, acc[t]);
            acc[t] = fmaf(e.z, wa.z, acc[t]);
            acc[t] = fmaf(e.w, wa.w, acc[t]);
        }
    }
    __syncthreads();                        // enc_s reads done (red aliases it)

    #pragma unroll
    for (int t = 0; t < NWMAX; t++) sm.w.u.r.red[t][kq][cl] = acc[t];

    // wait for prenet pout (overlapped with the matvec above; usually instant)
    if (tid == 0) {
        volatile unsigned* v2 = &d_cnt2;
        while (*v2 < NPRE) { __nanosleep(32); }
        unsigned old2 = atomicAdd(&d_cnt2b, 1u);          // consumed handshake
        if (old2 == NWB - 1) { d_cnt2 = 0; d_cnt2b = 0; } // all passed -> reset
    }
    __syncthreads();
    __threadfence();

    // bias slice: pout[b] @ W_dec[:, c0..c0+16) + bias0
    {
        const int c = tid & 15, q = tid >> 4;             // 16 splits of 32 k
        float bacc = 0.f;
        #pragma unroll 8
        for (int j = 0; j < 32; j++) {
            int k = q * 32 + j;
            bacc = fmaf(__ldcg(&d_pout[k][b]), W_dec[k * ATT_H + c0 + c], bacc);
        }
        sm.w.u.r.bias_red[q][c] = bacc;
    }
    __syncthreads();
    if (tid < NCG) {
        float s = __ldcg(&d_bias0[b][c0 + tid]);
        #pragma unroll
        for (int q = 0; q < 16; q++) s += sm.w.u.r.bias_red[q][tid];
        sm.w.bias_s[tid] = s;
    }
    __syncthreads();

    // tail: warp w8 handles t = pss*8 + w8
    {
        const int lane = tid & 31, w8 = tid >> 5;
        const int cl2 = lane & 15;
        #pragma unroll
        for (int pss = 0; pss < 3; pss++) {
            const int t = pss * 8 + w8;
            float v = 0.f;
            if (t < NWMAX) {
                float s = 0.f;
                #pragma unroll
                for (int q = 0; q < 16; q++) s += sm.w.u.r.red[t][q][cl2];
                s += sm.w.benc[cl2];
                s = s / (1.f + fabsf(s));                 // softsign
                s += sm.w.bias_s[cl2];
                float cv = 0.f;
                #pragma unroll
                for (int j = 0; j < KW; j++)
                    cv = fmaf(sm.w.pa_s[t + j], sm.w.convw[cl2 * KW + j], cv);
                s += cv;
                v = tanhf(s) * sm.w.wproj[cl2];
                if (lane >= 16) v = 0.f;                  // upper half contributes 0
            }
            #pragma unroll
            for (int o = 8; o > 0; o >>= 1) v += __shfl_xor_sync(0xffffffffu, v, o);
            if (lane == 0 && t < nwin) d_logit_part[b][t][cg] = v;
        }
    }

    // last-of-16 softmax
    __threadfence();
    __syncthreads();
    if (tid == 0) {
        unsigned old = atomicAdd(&d_count[b], 1u);
        last_s = (old == NCG - 1) ? 1 : 0;
    }
    __syncthreads();
    if (last_s) {
        if (tid < 32) {
            const int t = tid;
            float lg = -1e30f;
            if (t < nwin) {
                float s = 0.f;
                #pragma unroll
                for (int q = 0; q < NCG; q++) s += __ldcg(&d_logit_part[b][t][q]);
                lg = s;
            }
            float m = lg;
            #pragma unroll
            for (int o = 16; o > 0; o >>= 1) m = fmaxf(m, __shfl_xor_sync(0xffffffffu, m, o));
            float e = (t < nwin) ? expf(lg - m) : 0.f;
            float sum = e;
            #pragma unroll
            for (int o = 16; o > 0; o >>= 1) sum += __shfl_xor_sync(0xffffffffu, sum, o);
            if (t < nwin) out[(size_t)b * TT + lo + t] = e / sum;
        }
        if (tid == 0) d_count[b] = 0u;                    // reset for next replay
    }
}

// ---------------------------------------------------------------------------
extern "C" void kernel_launch(void* const* d_in, const int* in_sizes, int n_in,
                              void* d_out, int out_size)
{
    const float* input_enc = (const float*)d_in[0];
    const float* input_dec = (const float*)d_in[1];
    const float* prev_att  = (const float*)d_in[2];
    const float* spkr      = (const float*)d_in[3];
    const int*   lengths   = (const int*)  d_in[4];
    const float* speed     = (const float*)d_in[5];
    const float* W_enc     = (const float*)d_in[6];
    const float* b_enc     = (const float*)d_in[7];
    const float* W_spkr    = (const float*)d_in[8];
    const float* conv_w    = (const float*)d_in[9];
    const float* W_dec     = (const float*)d_in[10];
    const float* W_speed   = (const float*)d_in[11];
    const float* Wp1       = (const float*)d_in[12];
    const float* bp1       = (const float*)d_in[13];
    const float* Wp2       = (const float*)d_in[14];
    const float* bp2       = (const float*)d_in[15];
    const float* W_proj    = (const float*)d_in[16];
    // d_in[17] = b_proj: constant shift, cancels in the masked softmax.

    k_fused<<<GRID, 256>>>(input_enc, input_dec, prev_att, spkr, lengths, speed,
                           W_enc, b_enc, W_spkr, conv_w, W_dec, W_speed,
                           Wp1, bp1, Wp2, bp2, W_proj, (float*)d_out);
}

// round 9
// speedup vs baseline: 1.3412x; 1.3412x over previous
#include <cuda_runtime.h>
#include <cstdint>

// Problem constants
#define NB     32
#define TT     4096
#define ENC_H  512
#define ATT_H  256
#define OUTD   80
#define SPK    64
#define KW     31
#define NWMAX  19
#define NCG    8                   // channel groups per batch (32 ch each)
#define GRID   256                 // 32 b x 8 cg; single wave at 2 blocks/SM

// Device scratch (zero-init; all counters self-reset each call)
__device__ unsigned d_cnt1 = 0, d_cnt1b = 0;    // h ready / handshake
__device__ unsigned d_cnt2 = 0, d_cnt2b = 0;    // p2 partials ready / handshake
__device__ unsigned d_count[NB];                // softmax gate
__device__ float    d_h[1024][NB];              // prenet layer-1, k-major
__device__ float    d_p2part[NB][512][4];       // prenet layer-2 4-way split-K partials
__device__ float    d_logit_part[NB][NWMAX][NCG];

struct __align__(16) Smem {
    // enc window 19 x 512 (row stride 528); aliased after matvec as
    // red[t][kq][c]: offset t*528 + kq*33 + c  (kq<16, c<32; max 526 < 528)
    float enc[NWMAX * 528];
    union {
        float dec_s[8][145];                    // prenet1 inputs
        struct { float convw[32 * KW]; float benc[32]; float wproj[32]; } t;
    } v;
    float bias_red[8][33];
    float bias_s[32];
    float pa_s[NWMAX + 30 + 3];
    float wv[8]; int wi_[8];
    int sh_lo, sh_nwin, last_s;
};

__global__ __launch_bounds__(256, 2) void k_fused(
    const float* __restrict__ input_enc,
    const float* __restrict__ input_dec,
    const float* __restrict__ prev_att,
    const float* __restrict__ spkr,
    const int*   __restrict__ lengths,
    const float* __restrict__ speed,
    const float* __restrict__ W_enc,
    const float* __restrict__ b_enc,
    const float* __restrict__ W_spkr,
    const float* __restrict__ conv_w,
    const float* __restrict__ W_dec,
    const float* __restrict__ W_speed,
    const float* __restrict__ Wp1,
    const float* __restrict__ bp1,
    const float* __restrict__ Wp2,
    const float* __restrict__ bp2,
    const float* __restrict__ W_proj,
    float* __restrict__ out)
{
    __shared__ Smem sm;
    const int tid  = threadIdx.x;
    const int blk  = blockIdx.x;
    const int b    = blk >> 3;
    const int cg   = blk & 7;
    const int c0   = cg * 32;
    const int lane = tid & 31, wrp = tid >> 5;

    // ---- zero this block's output slice (512 floats) ----
    if (tid < 128)
        ((float4*)(out + (size_t)b * TT + cg * 512))[tid] =
            make_float4(0.f, 0.f, 0.f, 0.f);

    // ---- fast argmax: 16 elems/thread -> warp shuffle -> 8 leaders ----
    {
        const float4* pa4 = (const float4*)(prev_att + (size_t)b * TT);
        float bv = -1.f; int bi = 0;
        #pragma unroll
        for (int j = 0; j < 4; j++) {
            float4 v = pa4[tid * 4 + j];
            int base = tid * 16 + j * 4;
            if (v.x > bv) { bv = v.x; bi = base; }
            if (v.y > bv) { bv = v.y; bi = base + 1; }
            if (v.z > bv) { bv = v.z; bi = base + 2; }
            if (v.w > bv) { bv = v.w; bi = base + 3; }
        }
        #pragma unroll
        for (int o = 16; o > 0; o >>= 1) {
            float ov = __shfl_down_sync(0xffffffffu, bv, o);
            int   oi = __shfl_down_sync(0xffffffffu, bi, o);
            if (ov > bv || (ov == bv && oi < bi)) { bv = ov; bi = oi; }
        }
        if (lane == 0) { sm.wv[wrp] = bv; sm.wi_[wrp] = bi; }
    }
    __syncthreads();
    if (tid == 0) {
        float xv = sm.wv[0]; int xi = sm.wi_[0];
        #pragma unroll
        for (int j = 1; j < 8; j++) {
            float ov = sm.wv[j]; int oi = sm.wi_[j];
            if (ov > xv || (ov == xv && oi < xi)) { xv = ov; xi = oi; }
        }
        int lo = max(xi - 9, 0);
        int hi = min(xi + 9, lengths[b] - 1);
        sm.sh_lo = lo; sm.sh_nwin = hi - lo + 1;
    }
    __syncthreads();
    const int lo = sm.sh_lo, nwin = sm.sh_nwin;

    // ---- issue async enc-window copy (hidden behind prenet below) ----
    {
        const float4* enc4 = (const float4*)(input_enc + (size_t)b * TT * ENC_H);
        #pragma unroll
        for (int r = 0; r < 10; r++) {
            int i = tid + r * 256;
            if (i < NWMAX * 128) {
                int t = i >> 7, q = i & 127;
                int row = lo + t; if (row > TT - 1) row = TT - 1;   // clamped; unused t>=nwin
                uint32_t sa = (uint32_t)__cvta_generic_to_shared(&sm.enc[t * 528 + q * 4]);
                const void* ga = &enc4[(size_t)row * 128 + q];
                asm volatile("cp.async.cg.shared.global [%0], [%1], 16;\n" :: "r"(sa), "l"(ga));
            }
        }
        asm volatile("cp.async.commit_group;\n" ::);
    }

    // ---- L2 prefetch of W_enc / W_dec distinct slices ----
    {
        float pf = 0.f;
        if (tid < 128) {
            float4 a = __ldcg(&((const float4*)W_enc)[blk * 128 + tid]);
            float4 c = __ldcg(&((const float4*)W_dec)[blk * 128 + tid]);
            pf = a.x + c.x;
        }
        asm volatile("" :: "f"(pf));
    }

    // ---- pa halo (needed only in tail) ----
    for (int i = tid; i < nwin + 30; i += 256) {
        int p = lo - 15 + i;
        sm.pa_s[i] = (p >= 0 && p < TT) ? prev_att[(size_t)b * TT + p] : 0.f;
    }

    // ---- prenet1: h channels [c1,c1+16) x batches [b0,b0+8) ----
    {
        const int c1 = (blk & 63) * 16;
        const int b0 = (blk >> 6) * 8;
        for (int i = tid; i < 8 * 144; i += 256) {
            int bb = i / 144, k = i - bb * 144;
            sm.v.dec_s[bb][k] = (k < OUTD) ? input_dec[(b0 + bb) * OUTD + k]
                                           : spkr[(b0 + bb) * SPK + (k - OUTD)];
        }
        __syncthreads();
        const int cc = tid & 15, ss = (tid >> 4) & 1, bb = tid >> 5;
        float acc = 0.f;
        #pragma unroll 8
        for (int k = ss * 72; k < ss * 72 + 72; k++)
            acc = fmaf(sm.v.dec_s[bb][k], Wp1[k * 1024 + c1 + cc], acc);
        acc += __shfl_xor_sync(0xffffffffu, acc, 16);
        if (ss == 0)
            d_h[c1 + cc][b0 + bb] = fmaxf(acc + bp1[c1 + cc], 0.f);
    }
    __threadfence();
    __syncthreads();
    if (tid == 0) atomicAdd(&d_cnt1, 1u);

    // ---- load conv weights / small vectors (dec_s region now free) ----
    for (int i = tid; i < 32 * KW; i += 256) sm.v.t.convw[i] = conv_w[c0 * KW + i];
    if (tid < 32) {
        sm.v.t.benc[tid]  = b_enc[c0 + tid];
        sm.v.t.wproj[tid] = W_proj[c0 + tid];
    }

    // ---- wait h ready ----
    if (tid == 0) {
        volatile unsigned* v1 = &d_cnt1;
        while (*v1 < GRID) { __nanosleep(32); }
    }
    __syncthreads();
    __threadfence();

    // ---- prenet2 split-K partial: block = (16 cgroups) x (4 ksplits) x (4 bgroups)
    //      thread = (c = tid&31) x (bb = tid>>5); 256 FMA each ----
    {
        const int cb   = (blk & 15) * 32;
        const int ks   = (blk >> 4) & 3;
        const int b0   = (blk >> 6) * 8;
        const int c    = tid & 31;
        const int bb   = tid >> 5;
        const int kbeg = ks * 256;
        float acc = 0.f;
        #pragma unroll 4
        for (int j = 0; j < 256; j++) {
            int k = kbeg + j;
            float hv = __ldcg(&d_h[k][b0 + bb]);                    // warp-uniform bcast
            acc = fmaf(hv, Wp2[(size_t)k * 512 + cb + c], acc);     // coalesced
        }
        d_p2part[b0 + bb][cb + c][ks] = acc;
    }
    __threadfence();
    __syncthreads();
    if (tid == 0) {
        atomicAdd(&d_cnt2, 1u);
        unsigned o1 = atomicAdd(&d_cnt1b, 1u);          // all passed cnt1 spin
        if (o1 == GRID - 1) { d_cnt1 = 0; d_cnt1b = 0; }
    }

    // ---- matvec (FFMA2 over k-pairs), enc via completed cp.async ----
    asm volatile("cp.async.wait_group 0;\n" ::);
    __syncthreads();

    const int cl  = tid & 15;
    const int kq  = tid >> 4;
    const int ca  = c0 + cl;
    const int cb2 = ca + 16;

    unsigned long long acc_a[NWMAX], acc_b[NWMAX];
    #pragma unroll
    for (int t = 0; t < NWMAX; t++) { acc_a[t] = 0ull; acc_b[t] = 0ull; }

    #pragma unroll
    for (int k4 = 0; k4 < 8; k4++) {
        const int k = kq * 32 + k4 * 4;
        float w0a = W_enc[(k + 0) * ATT_H + ca],  w1a = W_enc[(k + 1) * ATT_H + ca];
        float w2a = W_enc[(k + 2) * ATT_H + ca],  w3a = W_enc[(k + 3) * ATT_H + ca];
        float w0b = W_enc[(k + 0) * ATT_H + cb2], w1b = W_enc[(k + 1) * ATT_H + cb2];
        float w2b = W_enc[(k + 2) * ATT_H + cb2], w3b = W_enc[(k + 3) * ATT_H + cb2];
        unsigned long long wa01, wa23, wb01, wb23;
        asm("mov.b64 %0,{%1,%2};" : "=l"(wa01) : "f"(w0a), "f"(w1a));
        asm("mov.b64 %0,{%1,%2};" : "=l"(wa23) : "f"(w2a), "f"(w3a));
        asm("mov.b64 %0,{%1,%2};" : "=l"(wb01) : "f"(w0b), "f"(w1b));
        asm("mov.b64 %0,{%1,%2};" : "=l"(wb23) : "f"(w2b), "f"(w3b));
        #pragma unroll
        for (int t = 0; t < NWMAX; t++) {
            ulonglong2 e = *(const ulonglong2*)&sm.enc[t * 528 + k];    // LDS.128
            asm("fma.rn.f32x2 %0,%1,%2,%0;" : "+l"(acc_a[t]) : "l"(e.x), "l"(wa01));
            asm("fma.rn.f32x2 %0,%1,%2,%0;" : "+l"(acc_a[t]) : "l"(e.y), "l"(wa23));
            asm("fma.rn.f32x2 %0,%1,%2,%0;" : "+l"(acc_b[t]) : "l"(e.x), "l"(wb01));
            asm("fma.rn.f32x2 %0,%1,%2,%0;" : "+l"(acc_b[t]) : "l"(e.y), "l"(wb23));
        }
    }
    __syncthreads();                        // enc reads done -> region becomes red

    #pragma unroll
    for (int t = 0; t < NWMAX; t++) {
        float l0, h0;
        asm("mov.b64 {%0,%1},%2;" : "=f"(l0), "=f"(h0) : "l"(acc_a[t]));
        sm.enc[t * 528 + kq * 33 + cl] = l0 + h0;
        asm("mov.b64 {%0,%1},%2;" : "=f"(l0), "=f"(h0) : "l"(acc_b[t]));
        sm.enc[t * 528 + kq * 33 + cl + 16] = l0 + h0;
    }

    // ---- wait p2 partials (overlapped with matvec; usually already set) ----
    if (tid == 0) {
        volatile unsigned* v2 = &d_cnt2;
        while (*v2 < GRID) { __nanosleep(32); }
        unsigned o2 = atomicAdd(&d_cnt2b, 1u);
        if (o2 == GRID - 1) { d_cnt2 = 0; d_cnt2b = 0; }
    }
    __syncthreads();
    __threadfence();

    // ---- bias slice: relu(bp2 + sum4 partials) @ W_dec[:, c0..c0+32) ----
    {
        const int c2 = tid & 31, q = tid >> 5;          // 8 splits of 64 k
        float bacc = 0.f;
        #pragma unroll 8
        for (int j = 0; j < 64; j++) {
            int k = q * 64 + j;
            float4 pp = __ldcg((const float4*)&d_p2part[b][k][0]);  // warp-uniform
            float pv = fmaxf(pp.x + pp.y + pp.z + pp.w + bp2[k], 0.f);
            bacc = fmaf(pv, W_dec[k * ATT_H + c0 + c2], bacc);
        }
        sm.bias_red[q][c2] = bacc;
    }
    __syncthreads();
    if (tid < 32) {
        float sa = 0.f;
        #pragma unroll 8
        for (int k = 0; k < SPK; k++)
            sa = fmaf(spkr[b * SPK + k], W_spkr[k * ATT_H + c0 + tid], sa);
        float s = sa / (1.f + fabsf(sa));               // spkr softsign bias
        s = fmaf(speed[b], W_speed[c0 + tid], s);       // speed bias
        #pragma unroll
        for (int q = 0; q < 8; q++) s += sm.bias_red[q][tid];
        sm.bias_s[tid] = s;
    }
    __syncthreads();

    // ---- tail: warp wrp handles t = p*8 + wrp ----
    #pragma unroll
    for (int p = 0; p < 3; p++) {
        const int t = p * 8 + wrp;
        float v = 0.f;
        if (t < NWMAX) {
            float s = 0.f;
            #pragma unroll
            for (int q = 0; q < 16; q++) s += sm.enc[t * 528 + q * 33 + lane];
            s += sm.v.t.benc[lane];
            s = s / (1.f + fabsf(s));                   // softsign(enc@W_enc + b_enc)
            s += sm.bias_s[lane];
            float cv = 0.f;
            #pragma unroll
            for (int j = 0; j < KW; j++)
                cv = fmaf(sm.pa_s[t + j], sm.v.t.convw[lane * KW + j], cv);
            s += cv;
            v = tanhf(s) * sm.v.t.wproj[lane];
        }
        #pragma unroll
        for (int o = 16; o > 0; o >>= 1) v += __shfl_down_sync(0xffffffffu, v, o);
        if (lane == 0 && t < nwin) d_logit_part[b][t][cg] = v;
    }

    // ---- last-of-8 fused softmax ----
    __threadfence();
    __syncthreads();
    if (tid == 0) {
        unsigned old = atomicAdd(&d_count[b], 1u);
        sm.last_s = (old == NCG - 1) ? 1 : 0;
    }
    __syncthreads();
    if (sm.last_s) {
        if (tid < 32) {
            const int t = tid;
            float lg = -1e30f;
            if (t < nwin) {
                float s = 0.f;
                #pragma unroll
                for (int q = 0; q < NCG; q++) s += __ldcg(&d_logit_part[b][t][q]);
                lg = s;
            }
            float m = lg;
            #pragma unroll
            for (int o = 16; o > 0; o >>= 1) m = fmaxf(m, __shfl_xor_sync(0xffffffffu, m, o));
            float e = (t < nwin) ? expf(lg - m) : 0.f;
            float sum = e;
            #pragma unroll
            for (int o = 16; o > 0; o >>= 1) sum += __shfl_xor_sync(0xffffffffu, sum, o);
            if (t < nwin) out[(size_t)b * TT + lo + t] = e / sum;
        }
        if (tid == 0) d_count[b] = 0u;                  // reset for next replay
    }
}

// ---------------------------------------------------------------------------
extern "C" void kernel_launch(void* const* d_in, const int* in_sizes, int n_in,
                              void* d_out, int out_size)
{
    const float* input_enc = (const float*)d_in[0];
    const float* input_dec = (const float*)d_in[1];
    const float* prev_att  = (const float*)d_in[2];
    const float* spkr      = (const float*)d_in[3];
    const int*   lengths   = (const int*)  d_in[4];
    const float* speed     = (const float*)d_in[5];
    const float* W_enc     = (const float*)d_in[6];
    const float* b_enc     = (const float*)d_in[7];
    const float* W_spkr    = (const float*)d_in[8];
    const float* conv_w    = (const float*)d_in[9];
    const float* W_dec     = (const float*)d_in[10];
    const float* W_speed   = (const float*)d_in[11];
    const float* Wp1       = (const float*)d_in[12];
    const float* bp1       = (const float*)d_in[13];
    const float* Wp2       = (const float*)d_in[14];
    const float* bp2       = (const float*)d_in[15];
    const float* W_proj    = (const float*)d_in[16];
    // d_in[17] = b_proj: constant shift, cancels in the masked softmax.

    k_fused<<<GRID, 256>>>(input_enc, input_dec, prev_att, spkr, lengths, speed,
                           W_enc, b_enc, W_spkr, conv_w, W_dec, W_speed,
                           Wp1, bp1, Wp2, bp2, W_proj, (float*)d_out);
}

// round 10
// speedup vs baseline: 1.7020x; 1.2690x over previous
#include <cuda_runtime.h>
#include <cstdint>

// Problem constants
#define NB     32
#define TT     4096
#define ENC_H  512
#define ATT_H  256
#define OUTD   80
#define SPK    64
#define KW     31
#define NWMAX  19
#define GRID   256

// Device scratch (no allocations allowed)
__device__ unsigned bar_cnt = 0;
__device__ unsigned bar_gen = 0;                 // monotonic across replays
__device__ unsigned d_cnt2  = 0;                 // prenet2 producer counter
__device__ float    d_argval[NB][8];
__device__ int      d_argidx[NB][8];
__device__ unsigned d_count[NB];
__device__ float    d_bias0[NB][ATT_H];
__device__ float    d_h[1024][NB];               // prenet layer-1, k-major
__device__ float    d_p2part[16][NB][512];       // prenet layer-2 split-K partials
__device__ float    d_logit_part[NB][NWMAX][8];

// grid-wide sense barrier (all GRID blocks co-resident: 2 blocks/SM)
__device__ __forceinline__ void grid_sync()
{
    __syncthreads();
    if (threadIdx.x == 0) {
        volatile unsigned* vg = &bar_gen;
        unsigned gen = *vg;
        __threadfence();
        if (atomicAdd(&bar_cnt, 1u) == GRID - 1) {
            bar_cnt = 0;
            __threadfence();
            atomicAdd(&bar_gen, 1u);
        } else {
            while (*vg == gen) { __nanosleep(32); }
        }
        __threadfence();
    }
    __syncthreads();
}

union SmemU {
    struct {                                // phase A
        float rv[128]; int ri[128];
        float dec_s[8][145];
        float w_s[144][16];
    } a;
    struct {                                // prenet2 (64-k slice)
        float h_s[64][33];
        float wt[64][36];
    } b;
    struct {                                // window (total < 48KB)
        union {
            float enc_s[NWMAX][516];        // full 512-k window, float4 rows
            float red_s[NWMAX][8][33];      // written only after matvec
        } u;
        float p_s[512];
        float bias_red[8][33];
        float pa_s[NWMAX + 30 + 3];
        float convw_s[32 * KW];
        float bias_s[32], benc_s[32], wproj_s[32];
    } c;
};

__global__ __launch_bounds__(256, 2) void k_fused(
    const float* __restrict__ input_enc,
    const float* __restrict__ input_dec,
    const float* __restrict__ prev_att,
    const float* __restrict__ spkr,
    const int*   __restrict__ lengths,
    const float* __restrict__ speed,
    const float* __restrict__ W_enc,
    const float* __restrict__ b_enc,
    const float* __restrict__ W_spkr,
    const float* __restrict__ conv_w,
    const float* __restrict__ W_dec,
    const float* __restrict__ W_speed,
    const float* __restrict__ Wp1,
    const float* __restrict__ bp1,
    const float* __restrict__ Wp2,
    const float* __restrict__ bp2,
    const float* __restrict__ W_proj,
    float* __restrict__ out)
{
    __shared__ SmemU sm;
    __shared__ int last_s, sh_lo, sh_nwin;
    const int tid = threadIdx.x;
    const int blk = blockIdx.x;
    const int b  = blk >> 3;                // batch for argmax/zero/window
    const int cg = blk & 7;                 // channel group for window

    // ============================ PHASE A ============================
    {
        if (blk == 0 && tid == 0) d_cnt2 = 0u;
        if (cg == 0 && tid == 0) d_count[b] = 0u;

        // zero output chunk (512 floats)
        if (tid < 128) {
            ((float4*)(out + (size_t)b * TT + cg * 512))[tid] =
                make_float4(0.f, 0.f, 0.f, 0.f);
        }

        // argmax partial over chunk [cg*512, cg*512+512), first max wins
        if (tid < 128) {
            const float4* pa4 = (const float4*)(prev_att + (size_t)b * TT + cg * 512);
            float4 v = pa4[tid];
            float bv = v.x; int bi = 0;
            if (v.y > bv) { bv = v.y; bi = 1; }
            if (v.z > bv) { bv = v.z; bi = 2; }
            if (v.w > bv) { bv = v.w; bi = 3; }
            sm.a.rv[tid] = bv;
            sm.a.ri[tid] = cg * 512 + tid * 4 + bi;
        }

        // L2 prefetch slice of W_enc (512KB / 256 blocks)
        float pf = 0.f;
        if (tid < 128) {
            float4 w = __ldcg(&((const float4*)W_enc)[blk * 128 + tid]);
            pf = w.x + w.y + w.z + w.w;
        }
        asm volatile("" :: "f"(pf));

        // prenet1: this block handles channels [c1, c1+16) x batches [b0, b0+8)
        const int c1 = (blk & 63) * 16;
        const int b0 = (blk >> 6) * 8;
        for (int i = tid; i < 8 * 144; i += 256) {
            int bb = i / 144, k = i - bb * 144;
            sm.a.dec_s[bb][k] = (k < OUTD) ? input_dec[(b0 + bb) * OUTD + k]
                                           : spkr[(b0 + bb) * SPK + (k - OUTD)];
        }
        for (int i = tid; i < 144 * 16; i += 256) {
            int k = i >> 4, cc = i & 15;
            sm.a.w_s[k][cc] = Wp1[k * 1024 + c1 + cc];
        }
        __syncthreads();

        // argmax reduce 128 -> 1
        for (int s = 64; s > 0; s >>= 1) {
            if (tid < s) {
                float ov = sm.a.rv[tid + s]; int oi = sm.a.ri[tid + s];
                if (ov > sm.a.rv[tid] || (ov == sm.a.rv[tid] && oi < sm.a.ri[tid])) {
                    sm.a.rv[tid] = ov; sm.a.ri[tid] = oi;
                }
            }
            __syncthreads();
        }
        if (tid == 0) { d_argval[b][cg] = sm.a.rv[0]; d_argidx[b][cg] = sm.a.ri[0]; }

        // prenet1 compute: bb = tid>>5, cc = (tid>>1)&15, ss = tid&1
        {
            const int bb = tid >> 5, cc = (tid >> 1) & 15, ss = tid & 1;
            float acc = 0.f;
            #pragma unroll 8
            for (int k = ss * 72; k < ss * 72 + 72; k++)
                acc = fmaf(sm.a.dec_s[bb][k], sm.a.w_s[k][cc], acc);
            acc += __shfl_xor_sync(0xffffffffu, acc, 1);
            if (ss == 0)
                d_h[c1 + cc][b0 + bb] = fmaxf(acc + bp1[c1 + cc], 0.f);
        }

        // cg==0 block: spkr softsign + speed bias
        if (cg == 0) {
            float sa = 0.f;
            #pragma unroll 8
            for (int k = 0; k < SPK; k++)
                sa = fmaf(spkr[b * SPK + k], W_spkr[k * ATT_H + tid], sa);
            float v = sa / (1.f + fabsf(sa));
            d_bias0[b][tid] = fmaf(speed[b], W_speed[tid], v);
        }
    }

    grid_sync();

    // ============================ PHASE B: prenet2 slice =====================
    {
        const int cb = (blk & 15) * 32;
        const int ks = blk >> 4;
        const int k0 = ks * 64;
        const int bb = tid & 31;
        const int s  = tid >> 5;

        for (int i = tid; i < 32 * 64; i += 256) {
            int kk = i >> 5, b2 = i & 31;
            sm.b.h_s[kk][b2] = d_h[k0 + kk][b2];
        }
        for (int i = tid; i < 64 * 32; i += 256) {
            int kk = i >> 5, sc = i & 31;
            sm.b.wt[kk][sc] = Wp2[(k0 + kk) * 512 + cb + sc];
        }
        __syncthreads();

        float4 acc = make_float4(0.f, 0.f, 0.f, 0.f);
        #pragma unroll 8
        for (int kk = 0; kk < 64; kk++) {
            float hv = sm.b.h_s[kk][bb];
            float4 w = *(const float4*)&sm.b.wt[kk][s * 4];
            acc.x = fmaf(hv, w.x, acc.x);
            acc.y = fmaf(hv, w.y, acc.y);
            acc.z = fmaf(hv, w.z, acc.z);
            acc.w = fmaf(hv, w.w, acc.w);
        }
        *(float4*)&d_p2part[ks][bb][cb + s * 4] = acc;

        __threadfence();
        __syncthreads();
        if (tid == 0) atomicAdd(&d_cnt2, 1u);
    }
    __syncthreads();                        // smem union switch b -> c

    // ============================ PHASE C: window ============================
    {
        const int c0 = cg * 32;

        if (tid == 0) {
            float bv = d_argval[b][0]; int bi = d_argidx[b][0];
            #pragma unroll
            for (int j = 1; j < 8; j++) {
                float v = d_argval[b][j];
                if (v > bv) { bv = v; bi = d_argidx[b][j]; }
            }
            int lo = max(bi - 9, 0);
            int hi = min(bi + 9, lengths[b] - 1);
            sh_lo = lo;
            sh_nwin = hi - lo + 1;
        }
        __syncthreads();
        const int lo   = sh_lo;
        const int nwin = sh_nwin;

        // stage the FULL enc window once: 19 rows x 128 float4
        const float4* enc4 = (const float4*)(input_enc + (size_t)b * TT * ENC_H);
        for (int i = tid; i < NWMAX * 128; i += 256) {
            int t = i >> 7, q = i & 127;
            int row = lo + t; if (row > TT - 1) row = TT - 1;   // clamped, unused t>=nwin
            float4 e = enc4[(size_t)row * (ENC_H / 4) + q];
            *(float4*)&sm.c.u.enc_s[t][q * 4] = e;
        }
        // small staging
        for (int i = tid; i < nwin + 30; i += 256) {
            int p = lo - 15 + i;
            sm.c.pa_s[i] = (p >= 0 && p < TT) ? prev_att[(size_t)b * TT + p] : 0.f;
        }
        for (int i = tid; i < 32 * KW; i += 256) sm.c.convw_s[i] = conv_w[c0 * KW + i];
        if (tid < 32) {
            sm.c.benc_s[tid]  = b_enc[c0 + tid];
            sm.c.wproj_s[tid] = W_proj[c0 + tid];
        }
        __syncthreads();

        // enc matvec (FFMA2 over packed k-pairs):
        // cl = tid&15 -> channels c0+cl, c0+cl+16; kq = tid>>4 (16 splits of 32 k)
        const int cl  = tid & 15;
        const int kq  = tid >> 4;
        const int ca  = c0 + cl;
        const int cb2 = c0 + cl + 16;

        unsigned long long acc_a[NWMAX], acc_b[NWMAX];
        #pragma unroll
        for (int t = 0; t < NWMAX; t++) { acc_a[t] = 0ull; acc_b[t] = 0ull; }

        #pragma unroll
        for (int tile = 0; tile < 4; tile++) {
            #pragma unroll
            for (int k4 = 0; k4 < 2; k4++) {
                const int kk = tile * 128 + kq * 8 + k4 * 4;
                float w0a = W_enc[(kk + 0) * ATT_H + ca];
                float w1a = W_enc[(kk + 1) * ATT_H + ca];
                float w2a = W_enc[(kk + 2) * ATT_H + ca];
                float w3a = W_enc[(kk + 3) * ATT_H + ca];
                float w0b = W_enc[(kk + 0) * ATT_H + cb2];
                float w1b = W_enc[(kk + 1) * ATT_H + cb2];
                float w2b = W_enc[(kk + 2) * ATT_H + cb2];
                float w3b = W_enc[(kk + 3) * ATT_H + cb2];
                unsigned long long wa01, wa23, wb01, wb23;
                asm("mov.b64 %0,{%1,%2};" : "=l"(wa01) : "f"(w0a), "f"(w1a));
                asm("mov.b64 %0,{%1,%2};" : "=l"(wa23) : "f"(w2a), "f"(w3a));
                asm("mov.b64 %0,{%1,%2};" : "=l"(wb01) : "f"(w0b), "f"(w1b));
                asm("mov.b64 %0,{%1,%2};" : "=l"(wb23) : "f"(w2b), "f"(w3b));
                #pragma unroll
                for (int t = 0; t < NWMAX; t++) {
                    ulonglong2 e = *(const ulonglong2*)&sm.c.u.enc_s[t][kk];  // LDS.128
                    asm("fma.rn.f32x2 %0,%1,%2,%0;" : "+l"(acc_a[t]) : "l"(e.x), "l"(wa01));
                    asm("fma.rn.f32x2 %0,%1,%2,%0;" : "+l"(acc_a[t]) : "l"(e.y), "l"(wa23));
                    asm("fma.rn.f32x2 %0,%1,%2,%0;" : "+l"(acc_b[t]) : "l"(e.x), "l"(wb01));
                    asm("fma.rn.f32x2 %0,%1,%2,%0;" : "+l"(acc_b[t]) : "l"(e.y), "l"(wb23));
                }
            }
        }

        __syncthreads();                    // all enc_s reads done (red_s aliases it)

        // reduce packed pairs, combine the two kq halves within each warp
        const int w = tid >> 5;
        #pragma unroll
        for (int t = 0; t < NWMAX; t++) {
            float l0, h0, l1, h1;
            asm("mov.b64 {%0,%1},%2;" : "=f"(l0), "=f"(h0) : "l"(acc_a[t]));
            asm("mov.b64 {%0,%1},%2;" : "=f"(l1), "=f"(h1) : "l"(acc_b[t]));
            float fa = l0 + h0, fb = l1 + h1;
            float va = fa + __shfl_xor_sync(0xffffffffu, fa, 16);
            float vb = fb + __shfl_xor_sync(0xffffffffu, fb, 16);
            if ((tid & 31) < 16) {
                sm.c.u.red_s[t][w][cl]      = va;
                sm.c.u.red_s[t][w][cl + 16] = vb;
            }
        }

        // wait for prenet2 producers (overlapped with matvec; usually done)
        if (tid == 0) {
            volatile unsigned* vc = &d_cnt2;
            while (*vc < GRID) { __nanosleep(32); }
        }
        __syncthreads();
        __threadfence();

        // reconstruct pout = relu(bp2 + sum of 16 split-K partials)
        #pragma unroll
        for (int r = 0; r < 2; r++) {
            int k = tid + r * 256;
            float v = bp2[k];
            #pragma unroll
            for (int j = 0; j < 16; j++) v += __ldcg(&d_p2part[j][b][k]);
            sm.c.p_s[k] = fmaxf(v, 0.f);
        }
        __syncthreads();

        // bias slice: pout @ W_dec[:, c0..c0+32) + bias0
        {
            const int cl2 = tid & 31, kq2 = tid >> 5;
            float acc = 0.f;
            #pragma unroll 8
            for (int j = 0; j < 64; j++) {
                int k = kq2 * 64 + j;
                acc = fmaf(sm.c.p_s[k], W_dec[k * ATT_H + c0 + cl2], acc);
            }
            sm.c.bias_red[kq2][cl2] = acc;
        }
        __syncthreads();
        if (tid < 32) {
            float s = d_bias0[b][c0 + tid];
            #pragma unroll
            for (int q = 0; q < 8; q++) s += sm.c.bias_red[q][tid];
            sm.c.bias_s[tid] = s;
        }
        __syncthreads();

        // parallel tail: warp tq handles t = p*8 + tq
        const int c2 = tid & 31;
        const int tq = tid >> 5;
        #pragma unroll
        for (int p = 0; p < 3; p++) {
            const int t = p * 8 + tq;
            float v = 0.f;
            if (t < nwin) {
                float s = 0.f;
                #pragma unroll
                for (int q = 0; q < 8; q++) s += sm.c.u.red_s[t][q][c2];
                s += sm.c.benc_s[c2];
                s = s / (1.f + fabsf(s));
                s += sm.c.bias_s[c2];
                float cv = 0.f;
                #pragma unroll
                for (int j = 0; j < KW; j++)
                    cv = fmaf(sm.c.pa_s[t + j], sm.c.convw_s[c2 * KW + j], cv);
                s += cv;
                v = tanhf(s) * sm.c.wproj_s[c2];
            }
            #pragma unroll
            for (int o = 16; o > 0; o >>= 1) v += __shfl_down_sync(0xffffffffu, v, o);
            if (c2 == 0 && t < nwin) d_logit_part[b][t][cg] = v;
        }

        // last-block-done fused softmax
        __threadfence();
        __syncthreads();
        if (tid == 0) {
            unsigned old = atomicAdd(&d_count[b], 1u);
            last_s = (old == 7u) ? 1 : 0;
        }
        __syncthreads();
        if (last_s && tid < 32) {
            const int t = tid;
            float lg = -1e30f;
            if (t < nwin) {
                float s = 0.f;
                #pragma unroll
                for (int q = 0; q < 8; q++) s += __ldcg(&d_logit_part[b][t][q]);
                lg = s;
            }
            float m = lg;
            #pragma unroll
            for (int o = 16; o > 0; o >>= 1) m = fmaxf(m, __shfl_xor_sync(0xffffffffu, m, o));
            float e = (t < nwin) ? expf(lg - m) : 0.f;
            float sum = e;
            #pragma unroll
            for (int o = 16; o > 0; o >>= 1) sum += __shfl_xor_sync(0xffffffffu, sum, o);
            if (t < nwin) out[(size_t)b * TT + lo + t] = e / sum;
        }
    }
}

// ---------------------------------------------------------------------------
extern "C" void kernel_launch(void* const* d_in, const int* in_sizes, int n_in,
                              void* d_out, int out_size)
{
    const float* input_enc = (const float*)d_in[0];
    const float* input_dec = (const float*)d_in[1];
    const float* prev_att  = (const float*)d_in[2];
    const float* spkr      = (const float*)d_in[3];
    const int*   lengths   = (const int*)  d_in[4];
    const float* speed     = (const float*)d_in[5];
    const float* W_enc     = (const float*)d_in[6];
    const float* b_enc     = (const float*)d_in[7];
    const float* W_spkr    = (const float*)d_in[8];
    const float* conv_w    = (const float*)d_in[9];
    const float* W_dec     = (const float*)d_in[10];
    const float* W_speed   = (const float*)d_in[11];
    const float* Wp1       = (const float*)d_in[12];
    const float* bp1       = (const float*)d_in[13];
    const float* Wp2       = (const float*)d_in[14];
    const float* bp2       = (const float*)d_in[15];
    const float* W_proj    = (const float*)d_in[16];
    // d_in[17] = b_proj: constant shift, cancels in the masked softmax.

    k_fused<<<GRID, 256>>>(input_enc, input_dec, prev_att, spkr, lengths, speed,
                           W_enc, b_enc, W_spkr, conv_w, W_dec, W_speed,
                           Wp1, bp1, Wp2, bp2, W_proj, (float*)d_out);
}

// round 11
// speedup vs baseline: 1.9252x; 1.1311x over previous
#include <cuda_runtime.h>
#include <cstdint>

// Problem constants
#define NB     32
#define TT     4096
#define ENC_H  512
#define ATT_H  256
#define OUTD   80
#define SPK    64
#define KW     31
#define NWMAX  19
#define GRID   256

// Device scratch (zero-init; self-resetting per call)
__device__ unsigned bar_cnt = 0;
__device__ unsigned bar_gen = 0;                 // monotonic across replays
__device__ unsigned d_cnt2  = 0;                 // prenet2 producer counter
__device__ unsigned d_count[NB];
__device__ float    d_bias0[NB][ATT_H];
__device__ float    d_h[1024][NB];               // prenet layer-1, k-major
__device__ float    d_p2part[16][NB][512];       // prenet layer-2 split-K partials
__device__ float    d_logit_part[NB][NWMAX][8];

// grid-wide sense barrier (all GRID blocks co-resident: 2 blocks/SM)
__device__ __forceinline__ void grid_sync()
{
    __syncthreads();
    if (threadIdx.x == 0) {
        volatile unsigned* vg = &bar_gen;
        unsigned gen = *vg;
        __threadfence();
        if (atomicAdd(&bar_cnt, 1u) == GRID - 1) {
            bar_cnt = 0;
            __threadfence();
            atomicAdd(&bar_gen, 1u);
        } else {
            while (*vg == gen) { __nanosleep(32); }
        }
        __threadfence();
    }
    __syncthreads();
}

struct __align__(16) Smem {
    // enc window 19 x 512, row stride 516 floats (2064B, 16B-aligned).
    // Aliased AFTER all matvec reads as red[t][w][c]: t*516 + w*33 + c (max 9550).
    float enc[NWMAX * 516];                      // 39,216 B (dedicated: cp.async target)
    union {
        float dec_s[8][145];                     // phase A prenet1 inputs
        struct {
            float p_s[512];
            float bias_red[8][33];
            float convw[32 * KW];
            float bias_s[32], benc[32], wproj[32];
        } t;                                     // phase C small
    } v;
    float pa_s[NWMAX + 30 + 3];
    float wv[8]; int wi_[8];
    int sh_lo, sh_nwin, last_s;
};

__global__ __launch_bounds__(256, 2) void k_fused(
    const float* __restrict__ input_enc,
    const float* __restrict__ input_dec,
    const float* __restrict__ prev_att,
    const float* __restrict__ spkr,
    const int*   __restrict__ lengths,
    const float* __restrict__ speed,
    const float* __restrict__ W_enc,
    const float* __restrict__ b_enc,
    const float* __restrict__ W_spkr,
    const float* __restrict__ conv_w,
    const float* __restrict__ W_dec,
    const float* __restrict__ W_speed,
    const float* __restrict__ Wp1,
    const float* __restrict__ bp1,
    const float* __restrict__ Wp2,
    const float* __restrict__ bp2,
    const float* __restrict__ W_proj,
    float* __restrict__ out)
{
    __shared__ Smem sm;
    const int tid  = threadIdx.x;
    const int blk  = blockIdx.x;
    const int b    = blk >> 3;
    const int cg   = blk & 7;
    const int c0   = cg * 32;
    const int lane = tid & 31, wrp = tid >> 5;

    // ============================ PHASE A ============================
    if (blk == 0 && tid == 0) d_cnt2 = 0u;
    if (cg == 0 && tid == 0) d_count[b] = 0u;

    // zero this block's output slice (512 floats)
    if (tid < 128)
        ((float4*)(out + (size_t)b * TT + cg * 512))[tid] =
            make_float4(0.f, 0.f, 0.f, 0.f);

    // full argmax of prev_att[b] (local; first max wins)
    {
        const float4* pa4 = (const float4*)(prev_att + (size_t)b * TT);
        float bv = -1.f; int bi = 0;
        #pragma unroll
        for (int j = 0; j < 4; j++) {
            float4 v = pa4[tid * 4 + j];
            int base = tid * 16 + j * 4;
            if (v.x > bv) { bv = v.x; bi = base; }
            if (v.y > bv) { bv = v.y; bi = base + 1; }
            if (v.z > bv) { bv = v.z; bi = base + 2; }
            if (v.w > bv) { bv = v.w; bi = base + 3; }
        }
        #pragma unroll
        for (int o = 16; o > 0; o >>= 1) {
            float ov = __shfl_down_sync(0xffffffffu, bv, o);
            int   oi = __shfl_down_sync(0xffffffffu, bi, o);
            if (ov > bv || (ov == bv && oi < bi)) { bv = ov; bi = oi; }
        }
        if (lane == 0) { sm.wv[wrp] = bv; sm.wi_[wrp] = bi; }
    }
    __syncthreads();
    if (tid == 0) {
        float xv = sm.wv[0]; int xi = sm.wi_[0];
        #pragma unroll
        for (int j = 1; j < 8; j++) {
            float ov = sm.wv[j]; int oi = sm.wi_[j];
            if (ov > xv || (ov == xv && oi < xi)) { xv = ov; xi = oi; }
        }
        int lo = max(xi - 9, 0);
        int hi = min(xi + 9, lengths[b] - 1);
        sm.sh_lo = lo; sm.sh_nwin = hi - lo + 1;
    }
    __syncthreads();
    const int lo = sm.sh_lo, nwin = sm.sh_nwin;

    // issue async enc-window copy NOW (hidden behind prenet + barrier below)
    {
        const float4* enc4 = (const float4*)(input_enc + (size_t)b * TT * ENC_H);
        #pragma unroll
        for (int r = 0; r < 10; r++) {
            int i = tid + r * 256;
            if (i < NWMAX * 128) {
                int t = i >> 7, q = i & 127;
                int row = lo + t; if (row > TT - 1) row = TT - 1;   // clamped; unused t>=nwin
                uint32_t sa = (uint32_t)__cvta_generic_to_shared(&sm.enc[t * 516 + q * 4]);
                const void* ga = &enc4[(size_t)row * 128 + q];
                asm volatile("cp.async.cg.shared.global [%0], [%1], 16;\n" :: "r"(sa), "l"(ga));
            }
        }
        asm volatile("cp.async.commit_group;\n" ::);
    }

    // L2 prefetch slice of W_enc
    {
        float pf = 0.f;
        if (tid < 128) {
            float4 w = __ldcg(&((const float4*)W_enc)[blk * 128 + tid]);
            pf = w.x + w.y + w.z + w.w;
        }
        asm volatile("" :: "f"(pf));
    }

    // pa halo (needs lo; consumed in the tail)
    for (int i = tid; i < nwin + 30; i += 256) {
        int p = lo - 15 + i;
        sm.pa_s[i] = (p >= 0 && p < TT) ? prev_att[(size_t)b * TT + p] : 0.f;
    }

    // prenet1: channels [c1,c1+16) x batches [b0,b0+8); Wp1 direct from global
    {
        const int c1 = (blk & 63) * 16;
        const int b0 = (blk >> 6) * 8;
        for (int i = tid; i < 8 * 144; i += 256) {
            int bb = i / 144, k = i - bb * 144;
            sm.v.dec_s[bb][k] = (k < OUTD) ? input_dec[(b0 + bb) * OUTD + k]
                                           : spkr[(b0 + bb) * SPK + (k - OUTD)];
        }
        __syncthreads();
        const int bb = tid >> 5, cc = (tid >> 1) & 15, ss = tid & 1;
        float acc = 0.f;
        #pragma unroll 8
        for (int k = ss * 72; k < ss * 72 + 72; k++)
            acc = fmaf(sm.v.dec_s[bb][k], Wp1[k * 1024 + c1 + cc], acc);
        acc += __shfl_xor_sync(0xffffffffu, acc, 1);
        if (ss == 0)
            d_h[c1 + cc][b0 + bb] = fmaxf(acc + bp1[c1 + cc], 0.f);
    }

    // cg==0 block: spkr softsign + speed bias
    if (cg == 0) {
        float sa = 0.f;
        #pragma unroll 8
        for (int k = 0; k < SPK; k++)
            sa = fmaf(spkr[b * SPK + k], W_spkr[k * ATT_H + tid], sa);
        float v = sa / (1.f + fabsf(sa));
        d_bias0[b][tid] = fmaf(speed[b], W_speed[tid], v);
    }

    grid_sync();                             // d_h, d_bias0 visible; dec_s dead

    // stage conv weights / small vectors (union region now phase-C)
    for (int i = tid; i < 32 * KW; i += 256) sm.v.t.convw[i] = conv_w[c0 * KW + i];
    if (tid < 32) {
        sm.v.t.benc[tid]  = b_enc[c0 + tid];
        sm.v.t.wproj[tid] = W_proj[c0 + tid];
    }

    // ============ PHASE B: prenet2 slice (global-direct, no smem) ============
    {
        const int cb = (blk & 15) * 32;
        const int k0 = (blk >> 4) * 64;
        const int bb = tid & 31;
        const int s  = tid >> 5;
        float4 acc = make_float4(0.f, 0.f, 0.f, 0.f);
        #pragma unroll 8
        for (int kk = 0; kk < 64; kk++) {
            float hv = __ldcg(&d_h[k0 + kk][bb]);                           // coalesced
            float4 w = *(const float4*)&Wp2[(size_t)(k0 + kk) * 512 + cb + s * 4]; // bcast
            acc.x = fmaf(hv, w.x, acc.x);
            acc.y = fmaf(hv, w.y, acc.y);
            acc.z = fmaf(hv, w.z, acc.z);
            acc.w = fmaf(hv, w.w, acc.w);
        }
        *(float4*)&d_p2part[blk >> 4][bb][cb + s * 4] = acc;
    }
    __threadfence();
    __syncthreads();
    if (tid == 0) atomicAdd(&d_cnt2, 1u);

    // ============================ PHASE C: window ============================
    // enc data: cp.async issued in phase A; wait and sync
    asm volatile("cp.async.wait_group 0;\n" ::);
    __syncthreads();

    // enc matvec (FFMA2 over packed k-pairs):
    // cl = tid&15 -> channels c0+cl, c0+cl+16; kq = tid>>4 (16 splits of 32 k)
    const int cl  = tid & 15;
    const int kq  = tid >> 4;
    const int ca  = c0 + cl;
    const int cb2 = c0 + cl + 16;

    unsigned long long acc_a[NWMAX], acc_b[NWMAX];
    #pragma unroll
    for (int t = 0; t < NWMAX; t++) { acc_a[t] = 0ull; acc_b[t] = 0ull; }

    #pragma unroll
    for (int k4 = 0; k4 < 8; k4++) {
        const int kk = kq * 32 + k4 * 4;
        float w0a = W_enc[(kk + 0) * ATT_H + ca];
        float w1a = W_enc[(kk + 1) * ATT_H + ca];
        float w2a = W_enc[(kk + 2) * ATT_H + ca];
        float w3a = W_enc[(kk + 3) * ATT_H + ca];
        float w0b = W_enc[(kk + 0) * ATT_H + cb2];
        float w1b = W_enc[(kk + 1) * ATT_H + cb2];
        float w2b = W_enc[(kk + 2) * ATT_H + cb2];
        float w3b = W_enc[(kk + 3) * ATT_H + cb2];
        unsigned long long wa01, wa23, wb01, wb23;
        asm("mov.b64 %0,{%1,%2};" : "=l"(wa01) : "f"(w0a), "f"(w1a));
        asm("mov.b64 %0,{%1,%2};" : "=l"(wa23) : "f"(w2a), "f"(w3a));
        asm("mov.b64 %0,{%1,%2};" : "=l"(wb01) : "f"(w0b), "f"(w1b));
        asm("mov.b64 %0,{%1,%2};" : "=l"(wb23) : "f"(w2b), "f"(w3b));
        #pragma unroll
        for (int t = 0; t < NWMAX; t++) {
            ulonglong2 e = *(const ulonglong2*)&sm.enc[t * 516 + kk];   // LDS.128 bcast
            asm("fma.rn.f32x2 %0,%1,%2,%0;" : "+l"(acc_a[t]) : "l"(e.x), "l"(wa01));
            asm("fma.rn.f32x2 %0,%1,%2,%0;" : "+l"(acc_a[t]) : "l"(e.y), "l"(wa23));
            asm("fma.rn.f32x2 %0,%1,%2,%0;" : "+l"(acc_b[t]) : "l"(e.x), "l"(wb01));
            asm("fma.rn.f32x2 %0,%1,%2,%0;" : "+l"(acc_b[t]) : "l"(e.y), "l"(wb23));
        }
    }
    __syncthreads();                        // all enc reads done -> region becomes red

    // reduce packed pairs, combine the two kq halves within each warp
    #pragma unroll
    for (int t = 0; t < NWMAX; t++) {
        float l0, h0, l1, h1;
        asm("mov.b64 {%0,%1},%2;" : "=f"(l0), "=f"(h0) : "l"(acc_a[t]));
        asm("mov.b64 {%0,%1},%2;" : "=f"(l1), "=f"(h1) : "l"(acc_b[t]));
        float fa = l0 + h0, fb = l1 + h1;
        float va = fa + __shfl_xor_sync(0xffffffffu, fa, 16);
        float vb = fb + __shfl_xor_sync(0xffffffffu, fb, 16);
        if (lane < 16) {
            sm.enc[t * 516 + wrp * 33 + cl]      = va;
            sm.enc[t * 516 + wrp * 33 + cl + 16] = vb;
        }
    }

    // wait for prenet2 producers (overlapped with matvec; usually already done)
    if (tid == 0) {
        volatile unsigned* vc = &d_cnt2;
        while (*vc < GRID) { __nanosleep(32); }
    }
    __syncthreads();
    __threadfence();

    // reconstruct pout = relu(bp2 + sum of 16 split-K partials)
    #pragma unroll
    for (int r = 0; r < 2; r++) {
        int k = tid + r * 256;
        float v = bp2[k];
        #pragma unroll
        for (int j = 0; j < 16; j++) v += __ldcg(&d_p2part[j][b][k]);
        sm.v.t.p_s[k] = fmaxf(v, 0.f);
    }
    __syncthreads();

    // bias slice: pout @ W_dec[:, c0..c0+32) + bias0
    {
        const int cl2 = tid & 31, kq2 = tid >> 5;
        float acc = 0.f;
        #pragma unroll 8
        for (int j = 0; j < 64; j++) {
            int k = kq2 * 64 + j;
            acc = fmaf(sm.v.t.p_s[k], W_dec[k * ATT_H + c0 + cl2], acc);
        }
        sm.v.t.bias_red[kq2][cl2] = acc;
    }
    __syncthreads();
    if (tid < 32) {
        float s = d_bias0[b][c0 + tid];
        #pragma unroll
        for (int q = 0; q < 8; q++) s += sm.v.t.bias_red[q][tid];
        sm.v.t.bias_s[tid] = s;
    }
    __syncthreads();

    // parallel tail: warp wrp handles t = p*8 + wrp
    #pragma unroll
    for (int p = 0; p < 3; p++) {
        const int t = p * 8 + wrp;
        float v = 0.f;
        if (t < nwin) {
            float s = 0.f;
            #pragma unroll
            for (int q = 0; q < 8; q++) s += sm.enc[t * 516 + q * 33 + lane];
            s += sm.v.t.benc[lane];
            s = s / (1.f + fabsf(s));                   // softsign(enc@W_enc + b_enc)
            s += sm.v.t.bias_s[lane];
            float cv = 0.f;
            #pragma unroll
            for (int j = 0; j < KW; j++)
                cv = fmaf(sm.pa_s[t + j], sm.v.t.convw[lane * KW + j], cv);
            s += cv;
            v = tanhf(s) * sm.v.t.wproj[lane];
        }
        #pragma unroll
        for (int o = 16; o > 0; o >>= 1) v += __shfl_down_sync(0xffffffffu, v, o);
        if (lane == 0 && t < nwin) d_logit_part[b][t][cg] = v;
    }

    // last-block-done fused softmax
    __threadfence();
    __syncthreads();
    if (tid == 0) {
        unsigned old = atomicAdd(&d_count[b], 1u);
        sm.last_s = (old == 7u) ? 1 : 0;
    }
    __syncthreads();
    if (sm.last_s && tid < 32) {
        const int t = tid;
        float lg = -1e30f;
        if (t < nwin) {
            float s = 0.f;
            #pragma unroll
            for (int q = 0; q < 8; q++) s += __ldcg(&d_logit_part[b][t][q]);
            lg = s;
        }
        float m = lg;
        #pragma unroll
        for (int o = 16; o > 0; o >>= 1) m = fmaxf(m, __shfl_xor_sync(0xffffffffu, m, o));
        float e = (t < nwin) ? expf(lg - m) : 0.f;
        float sum = e;
        #pragma unroll
        for (int o = 16; o > 0; o >>= 1) sum += __shfl_xor_sync(0xffffffffu, sum, o);
        if (t < nwin) out[(size_t)b * TT + lo + t] = e / sum;
    }
}

// ---------------------------------------------------------------------------
extern "C" void kernel_launch(void* const* d_in, const int* in_sizes, int n_in,
                              void* d_out, int out_size)
{
    const float* input_enc = (const float*)d_in[0];
    const float* input_dec = (const float*)d_in[1];
    const float* prev_att  = (const float*)d_in[2];
    const float* spkr      = (const float*)d_in[3];
    const int*   lengths   = (const int*)  d_in[4];
    const float* speed     = (const float*)d_in[5];
    const float* W_enc     = (const float*)d_in[6];
    const float* b_enc     = (const float*)d_in[7];
    const float* W_spkr    = (const float*)d_in[8];
    const float* conv_w    = (const float*)d_in[9];
    const float* W_dec     = (const float*)d_in[10];
    const float* W_speed   = (const float*)d_in[11];
    const float* Wp1       = (const float*)d_in[12];
    const float* bp1       = (const float*)d_in[13];
    const float* Wp2       = (const float*)d_in[14];
    const float* bp2       = (const float*)d_in[15];
    const float* W_proj    = (const float*)d_in[16];
    // d_in[17] = b_proj: constant shift, cancels in the masked softmax.

    k_fused<<<GRID, 256>>>(input_enc, input_dec, prev_att, spkr, lengths, speed,
                           W_enc, b_enc, W_spkr, conv_w, W_dec, W_speed,
                           Wp1, bp1, Wp2, bp2, W_proj, (float*)d_out);
}

// round 12
// speedup vs baseline: 2.0626x; 1.0714x over previous
#include <cuda_runtime.h>
#include <cstdint>

// Problem constants
#define NB     32
#define TT     4096
#define ENC_H  512
#define ATT_H  256
#define OUTD   80
#define SPK    64
#define KW     31
#define NWMAX  19
#define GRID   256

// Device scratch (zero-init; self-resetting per call)
__device__ unsigned bar_cnt = 0;
__device__ unsigned bar_gen = 0;                 // monotonic across replays
__device__ unsigned d_cnt2  = 0;                 // prenet2 producer counter
__device__ unsigned d_count[NB];
__device__ float    d_bias0[NB][ATT_H];
__device__ float    d_h[1024][NB];               // prenet layer-1, k-major
__device__ float    d_p2part[16][NB][512];       // prenet layer-2 split-K partials
__device__ float    d_logit_part[NB][NWMAX][8];

// grid-wide sense barrier (all GRID blocks co-resident: 2 blocks/SM)
__device__ __forceinline__ void grid_sync()
{
    __syncthreads();
    if (threadIdx.x == 0) {
        volatile unsigned* vg = &bar_gen;
        unsigned gen = *vg;
        __threadfence();
        if (atomicAdd(&bar_cnt, 1u) == GRID - 1) {
            bar_cnt = 0;
            __threadfence();
            atomicAdd(&bar_gen, 1u);
        } else {
            while (*vg == gen) { __nanosleep(32); }
        }
        __threadfence();
    }
    __syncthreads();
}

struct __align__(16) Smem {
    // enc window 19 x 512, row stride 516 floats (2064B, 16B-aligned).
    // Aliased AFTER all matvec reads as red[t][w][c]: t*516 + w*33 + c (max 9550).
    float enc[NWMAX * 516];                      // 39,216 B (dedicated: cp.async target)
    union {
        float dec_s[8][145];                     // phase A prenet1 inputs
        struct {
            float p_s[512];
            float bias_red[8][33];
            float convw[32 * KW];
            float bias_s[32], benc[32], wproj[32];
        } t;                                     // phase C small
    } v;
    float pa_s[NWMAX + 30 + 3];
    float wv[8]; int wi_[8];
    int sh_lo, sh_nwin, last_s;
};

__global__ __launch_bounds__(256, 2) void k_fused(
    const float* __restrict__ input_enc,
    const float* __restrict__ input_dec,
    const float* __restrict__ prev_att,
    const float* __restrict__ spkr,
    const int*   __restrict__ lengths,
    const float* __restrict__ speed,
    const float* __restrict__ W_enc,
    const float* __restrict__ b_enc,
    const float* __restrict__ W_spkr,
    const float* __restrict__ conv_w,
    const float* __restrict__ W_dec,
    const float* __restrict__ W_speed,
    const float* __restrict__ Wp1,
    const float* __restrict__ bp1,
    const float* __restrict__ Wp2,
    const float* __restrict__ bp2,
    const float* __restrict__ W_proj,
    float* __restrict__ out)
{
    __shared__ Smem sm;
    const int tid  = threadIdx.x;
    const int blk  = blockIdx.x;
    const int b    = blk >> 3;
    const int cg   = blk & 7;
    const int c0   = cg * 32;
    const int lane = tid & 31, wrp = tid >> 5;

    // ============================ PHASE A ============================
    if (blk == 0 && tid == 0) d_cnt2 = 0u;
    if (cg == 0 && tid == 0) d_count[b] = 0u;

    // zero this block's output slice (512 floats)
    if (tid < 128)
        ((float4*)(out + (size_t)b * TT + cg * 512))[tid] =
            make_float4(0.f, 0.f, 0.f, 0.f);

    // full argmax of prev_att[b] (local; first max wins)
    {
        const float4* pa4 = (const float4*)(prev_att + (size_t)b * TT);
        float bv = -1.f; int bi = 0;
        #pragma unroll
        for (int j = 0; j < 4; j++) {
            float4 v = pa4[tid * 4 + j];
            int base = tid * 16 + j * 4;
            if (v.x > bv) { bv = v.x; bi = base; }
            if (v.y > bv) { bv = v.y; bi = base + 1; }
            if (v.z > bv) { bv = v.z; bi = base + 2; }
            if (v.w > bv) { bv = v.w; bi = base + 3; }
        }
        #pragma unroll
        for (int o = 16; o > 0; o >>= 1) {
            float ov = __shfl_down_sync(0xffffffffu, bv, o);
            int   oi = __shfl_down_sync(0xffffffffu, bi, o);
            if (ov > bv || (ov == bv && oi < bi)) { bv = ov; bi = oi; }
        }
        if (lane == 0) { sm.wv[wrp] = bv; sm.wi_[wrp] = bi; }
    }
    __syncthreads();
    if (tid == 0) {
        float xv = sm.wv[0]; int xi = sm.wi_[0];
        #pragma unroll
        for (int j = 1; j < 8; j++) {
            float ov = sm.wv[j]; int oi = sm.wi_[j];
            if (ov > xv || (ov == xv && oi < xi)) { xv = ov; xi = oi; }
        }
        int lo = max(xi - 9, 0);
        int hi = min(xi + 9, lengths[b] - 1);
        sm.sh_lo = lo; sm.sh_nwin = hi - lo + 1;
    }
    __syncthreads();
    const int lo = sm.sh_lo, nwin = sm.sh_nwin;

    // issue async enc-window copy NOW (hidden behind prenet + barrier below)
    {
        const float4* enc4 = (const float4*)(input_enc + (size_t)b * TT * ENC_H);
        #pragma unroll
        for (int r = 0; r < 10; r++) {
            int i = tid + r * 256;
            if (i < NWMAX * 128) {
                int t = i >> 7, q = i & 127;
                int row = lo + t; if (row > TT - 1) row = TT - 1;   // clamped; unused t>=nwin
                uint32_t sa = (uint32_t)__cvta_generic_to_shared(&sm.enc[t * 516 + q * 4]);
                const void* ga = &enc4[(size_t)row * 128 + q];
                asm volatile("cp.async.cg.shared.global [%0], [%1], 16;\n" :: "r"(sa), "l"(ga));
            }
        }
        asm volatile("cp.async.commit_group;\n" ::);
    }

    // L2 prefetch: W_enc slice + Wp2 slice (Wp2 consumed by prenet2 after barrier)
    {
        float pf = 0.f;
        if (tid < 128) {
            float4 a = __ldcg(&((const float4*)W_enc)[blk * 128 + tid]);
            pf = a.x + a.y + a.z + a.w;
        }
        // Wp2: 1024x512 floats = 131072 float4; 256 blocks x 512 float4 = full cover
        {
            float4 w0 = __ldcg(&((const float4*)Wp2)[blk * 512 + tid]);
            float4 w1 = __ldcg(&((const float4*)Wp2)[blk * 512 + 256 + tid]);
            pf += w0.x + w1.x;
        }
        asm volatile("" :: "f"(pf));
    }

    // pa halo (needs lo; consumed in the tail)
    for (int i = tid; i < nwin + 30; i += 256) {
        int p = lo - 15 + i;
        sm.pa_s[i] = (p >= 0 && p < TT) ? prev_att[(size_t)b * TT + p] : 0.f;
    }

    // prenet1: channels [c1,c1+16) x batches [b0,b0+8); Wp1 direct from global
    {
        const int c1 = (blk & 63) * 16;
        const int b0 = (blk >> 6) * 8;
        for (int i = tid; i < 8 * 144; i += 256) {
            int bb = i / 144, k = i - bb * 144;
            sm.v.dec_s[bb][k] = (k < OUTD) ? input_dec[(b0 + bb) * OUTD + k]
                                           : spkr[(b0 + bb) * SPK + (k - OUTD)];
        }
        __syncthreads();
        const int bb = tid >> 5, cc = (tid >> 1) & 15, ss = tid & 1;
        float acc = 0.f;
        #pragma unroll 24
        for (int k = ss * 72; k < ss * 72 + 72; k++)
            acc = fmaf(sm.v.dec_s[bb][k], Wp1[k * 1024 + c1 + cc], acc);
        acc += __shfl_xor_sync(0xffffffffu, acc, 1);
        if (ss == 0)
            d_h[c1 + cc][b0 + bb] = fmaxf(acc + bp1[c1 + cc], 0.f);
    }

    // cg==0 block: spkr softsign + speed bias
    if (cg == 0) {
        float sa = 0.f;
        #pragma unroll 8
        for (int k = 0; k < SPK; k++)
            sa = fmaf(spkr[b * SPK + k], W_spkr[k * ATT_H + tid], sa);
        float v = sa / (1.f + fabsf(sa));
        d_bias0[b][tid] = fmaf(speed[b], W_speed[tid], v);
    }

    grid_sync();                             // d_h, d_bias0 visible; dec_s dead

    // stage conv weights / small vectors (union region now phase-C)
    for (int i = tid; i < 32 * KW; i += 256) sm.v.t.convw[i] = conv_w[c0 * KW + i];
    if (tid < 32) {
        sm.v.t.benc[tid]  = b_enc[c0 + tid];
        sm.v.t.wproj[tid] = W_proj[c0 + tid];
    }

    // ============ PHASE B: prenet2 slice (global-direct, full unroll) ============
    {
        const int cb = (blk & 15) * 32;
        const int k0 = (blk >> 4) * 64;
        const int bb = tid & 31;
        const int s  = tid >> 5;
        float4 acc = make_float4(0.f, 0.f, 0.f, 0.f);
        #pragma unroll
        for (int kk = 0; kk < 64; kk++) {
            float hv = __ldcg(&d_h[k0 + kk][bb]);                           // coalesced
            float4 w = *(const float4*)&Wp2[(size_t)(k0 + kk) * 512 + cb + s * 4]; // bcast
            acc.x = fmaf(hv, w.x, acc.x);
            acc.y = fmaf(hv, w.y, acc.y);
            acc.z = fmaf(hv, w.z, acc.z);
            acc.w = fmaf(hv, w.w, acc.w);
        }
        *(float4*)&d_p2part[blk >> 4][bb][cb + s * 4] = acc;
    }
    __threadfence();
    __syncthreads();
    if (tid == 0) atomicAdd(&d_cnt2, 1u);

    // ============================ PHASE C: window ============================
    // enc data: cp.async issued in phase A; wait and sync
    asm volatile("cp.async.wait_group 0;\n" ::);
    __syncthreads();

    // enc matvec (FFMA2 over packed k-pairs):
    // cl = tid&15 -> channels c0+cl, c0+cl+16; kq = tid>>4 (16 splits of 32 k)
    const int cl  = tid & 15;
    const int kq  = tid >> 4;
    const int ca  = c0 + cl;
    const int cb2 = c0 + cl + 16;

    unsigned long long acc_a[NWMAX], acc_b[NWMAX];
    #pragma unroll
    for (int t = 0; t < NWMAX; t++) { acc_a[t] = 0ull; acc_b[t] = 0ull; }

    #pragma unroll
    for (int k4 = 0; k4 < 8; k4++) {
        const int kk = kq * 32 + k4 * 4;
        float w0a = W_enc[(kk + 0) * ATT_H + ca];
        float w1a = W_enc[(kk + 1) * ATT_H + ca];
        float w2a = W_enc[(kk + 2) * ATT_H + ca];
        float w3a = W_enc[(kk + 3) * ATT_H + ca];
        float w0b = W_enc[(kk + 0) * ATT_H + cb2];
        float w1b = W_enc[(kk + 1) * ATT_H + cb2];
        float w2b = W_enc[(kk + 2) * ATT_H + cb2];
        float w3b = W_enc[(kk + 3) * ATT_H + cb2];
        unsigned long long wa01, wa23, wb01, wb23;
        asm("mov.b64 %0,{%1,%2};" : "=l"(wa01) : "f"(w0a), "f"(w1a));
        asm("mov.b64 %0,{%1,%2};" : "=l"(wa23) : "f"(w2a), "f"(w3a));
        asm("mov.b64 %0,{%1,%2};" : "=l"(wb01) : "f"(w0b), "f"(w1b));
        asm("mov.b64 %0,{%1,%2};" : "=l"(wb23) : "f"(w2b), "f"(w3b));
        #pragma unroll
        for (int t = 0; t < NWMAX; t++) {
            ulonglong2 e = *(const ulonglong2*)&sm.enc[t * 516 + kk];   // LDS.128 bcast
            asm("fma.rn.f32x2 %0,%1,%2,%0;" : "+l"(acc_a[t]) : "l"(e.x), "l"(wa01));
            asm("fma.rn.f32x2 %0,%1,%2,%0;" : "+l"(acc_a[t]) : "l"(e.y), "l"(wa23));
            asm("fma.rn.f32x2 %0,%1,%2,%0;" : "+l"(acc_b[t]) : "l"(e.x), "l"(wb01));
            asm("fma.rn.f32x2 %0,%1,%2,%0;" : "+l"(acc_b[t]) : "l"(e.y), "l"(wb23));
        }
    }
    __syncthreads();                        // all enc reads done -> region becomes red

    // reduce packed pairs, combine the two kq halves within each warp
    #pragma unroll
    for (int t = 0; t < NWMAX; t++) {
        float l0, h0, l1, h1;
        asm("mov.b64 {%0,%1},%2;" : "=f"(l0), "=f"(h0) : "l"(acc_a[t]));
        asm("mov.b64 {%0,%1},%2;" : "=f"(l1), "=f"(h1) : "l"(acc_b[t]));
        float fa = l0 + h0, fb = l1 + h1;
        float va = fa + __shfl_xor_sync(0xffffffffu, fa, 16);
        float vb = fb + __shfl_xor_sync(0xffffffffu, fb, 16);
        if (lane < 16) {
            sm.enc[t * 516 + wrp * 33 + cl]      = va;
            sm.enc[t * 516 + wrp * 33 + cl + 16] = vb;
        }
    }

    // wait for prenet2 producers (overlapped with matvec; usually already done)
    if (tid == 0) {
        volatile unsigned* vc = &d_cnt2;
        while (*vc < GRID) { __nanosleep(32); }
    }
    __syncthreads();
    __threadfence();

    // reconstruct pout = relu(bp2 + sum of 16 split-K partials)
    #pragma unroll
    for (int r = 0; r < 2; r++) {
        int k = tid + r * 256;
        float v = bp2[k];
        #pragma unroll
        for (int j = 0; j < 16; j++) v += __ldcg(&d_p2part[j][b][k]);
        sm.v.t.p_s[k] = fmaxf(v, 0.f);
    }
    __syncthreads();

    // bias slice: pout @ W_dec[:, c0..c0+32) + bias0  (full unroll for MLP)
    {
        const int cl2 = tid & 31, kq2 = tid >> 5;
        float acc = 0.f;
        #pragma unroll
        for (int j = 0; j < 64; j++) {
            int k = kq2 * 64 + j;
            acc = fmaf(sm.v.t.p_s[k], W_dec[k * ATT_H + c0 + cl2], acc);
        }
        sm.v.t.bias_red[kq2][cl2] = acc;
    }
    __syncthreads();
    if (tid < 32) {
        float s = d_bias0[b][c0 + tid];
        #pragma unroll
        for (int q = 0; q < 8; q++) s += sm.v.t.bias_red[q][tid];
        sm.v.t.bias_s[tid] = s;
    }
    __syncthreads();

    // parallel tail: warp wrp handles t = p*8 + wrp
    #pragma unroll
    for (int p = 0; p < 3; p++) {
        const int t = p * 8 + wrp;
        float v = 0.f;
        if (t < nwin) {
            float s = 0.f;
            #pragma unroll
            for (int q = 0; q < 8; q++) s += sm.enc[t * 516 + q * 33 + lane];
            s += sm.v.t.benc[lane];
            s = s / (1.f + fabsf(s));                   // softsign(enc@W_enc + b_enc)
            s += sm.v.t.bias_s[lane];
            float cv = 0.f;
            #pragma unroll
            for (int j = 0; j < KW; j++)
                cv = fmaf(sm.pa_s[t + j], sm.v.t.convw[lane * KW + j], cv);
            s += cv;
            v = tanhf(s) * sm.v.t.wproj[lane];
        }
        #pragma unroll
        for (int o = 16; o > 0; o >>= 1) v += __shfl_down_sync(0xffffffffu, v, o);
        if (lane == 0 && t < nwin) d_logit_part[b][t][cg] = v;
    }

    // last-block-done fused softmax
    __threadfence();
    __syncthreads();
    if (tid == 0) {
        unsigned old = atomicAdd(&d_count[b], 1u);
        sm.last_s = (old == 7u) ? 1 : 0;
    }
    __syncthreads();
    if (sm.last_s && tid < 32) {
        const int t = tid;
        float lg = -1e30f;
        if (t < nwin) {
            float s = 0.f;
            #pragma unroll
            for (int q = 0; q < 8; q++) s += __ldcg(&d_logit_part[b][t][q]);
            lg = s;
        }
        float m = lg;
        #pragma unroll
        for (int o = 16; o > 0; o >>= 1) m = fmaxf(m, __shfl_xor_sync(0xffffffffu, m, o));
        float e = (t < nwin) ? expf(lg - m) : 0.f;
        float sum = e;
        #pragma unroll
        for (int o = 16; o > 0; o >>= 1) sum += __shfl_xor_sync(0xffffffffu, sum, o);
        if (t < nwin) out[(size_t)b * TT + lo + t] = e / sum;
    }
}

// ---------------------------------------------------------------------------
extern "C" void kernel_launch(void* const* d_in, const int* in_sizes, int n_in,
                              void* d_out, int out_size)
{
    const float* input_enc = (const float*)d_in[0];
    const float* input_dec = (const float*)d_in[1];
    const float* prev_att  = (const float*)d_in[2];
    const float* spkr      = (const float*)d_in[3];
    const int*   lengths   = (const int*)  d_in[4];
    const float* speed     = (const float*)d_in[5];
    const float* W_enc     = (const float*)d_in[6];
    const float* b_enc     = (const float*)d_in[7];
    const float* W_spkr    = (const float*)d_in[8];
    const float* conv_w    = (const float*)d_in[9];
    const float* W_dec     = (const float*)d_in[10];
    const float* W_speed   = (const float*)d_in[11];
    const float* Wp1       = (const float*)d_in[12];
    const float* bp1       = (const float*)d_in[13];
    const float* Wp2       = (const float*)d_in[14];
    const float* bp2       = (const float*)d_in[15];
    const float* W_proj    = (const float*)d_in[16];
    // d_in[17] = b_proj: constant shift, cancels in the masked softmax.

    k_fused<<<GRID, 256>>>(input_enc, input_dec, prev_att, spkr, lengths, speed,
                           W_enc, b_enc, W_spkr, conv_w, W_dec, W_speed,
                           Wp1, bp1, Wp2, bp2, W_proj, (float*)d_out);
}